// round 13
// baseline (speedup 1.0000x reference)
#include <cuda_runtime.h>
#include <math.h>

#define B_ 4096
#define T_ 30
#define R_ (B_*T_)          // 122880 rows
#define H_ 256
#define G3_ 768
#define HC_ 32
#define GC3_ 96
#define PASSES 14
#define NLOGB (R_/8)        // 15360

// ----------------------------- scratch ------------------------------------
__device__ float g_GI0[(size_t)R_*G3_];
__device__ float g_GHA[(size_t)R_*G3_];   // gh0 / gh1 / comb(512) reuse
__device__ float g_GI1[(size_t)R_*G3_];   // gi1 / f1 reuse
__device__ float g_GIC[(size_t)R_*GC3_];
__device__ float g_GHC[(size_t)R_*GC3_];
__device__ float g_HP0[(size_t)R_*H_];
__device__ float g_HP1[(size_t)R_*H_];
__device__ float g_HPC[(size_t)R_*HC_];
__device__ float g_H0 [(size_t)R_*H_];
__device__ float g_H1 [(size_t)R_*H_];
__device__ float g_HC [(size_t)R_*HC_];
__device__ float g_S0[R_], g_S1[R_], g_SC[R_];
__device__ float g_A0[R_], g_A1[R_], g_AC[R_];
__device__ int   g_PREV[R_];
__device__ float g_partial[NLOGB];

__device__ __forceinline__ float wsum(float v){
  #pragma unroll
  for (int o=16;o;o>>=1) v += __shfl_xor_sync(0xffffffffu, v, o);
  return v;
}
__device__ __forceinline__ float wmax(float v){
  #pragma unroll
  for (int o=16;o;o>>=1) v = fmaxf(v, __shfl_xor_sync(0xffffffffu, v, o));
  return v;
}
__device__ __forceinline__ float sigm(float x){ return 1.f/(1.f+expf(-x)); }

// --------------------------- SGEMM (NT) ------------------------------------
// C[m,n] = sum_k A[m,k]*W[n,k] + bias[n], optional relu.
// M = gridDim.y*128 exactly; K%16==0; N bounds-checked; lda=K, ldc given.
__global__ void __launch_bounds__(256)
sgemm_nt(const float* __restrict__ A, const float* __restrict__ W,
         const float* __restrict__ bias, float* __restrict__ C,
         int N, int K, int ldc, int relu)
{
  __shared__ float As[16][132];
  __shared__ float Bs[16][132];
  const int m0 = blockIdx.y << 7;
  const int n0 = blockIdx.x << 7;
  const int tid = threadIdx.x;
  const int tx = tid & 15;
  const int ty = tid >> 4;
  float acc[8][8];
  #pragma unroll
  for (int i=0;i<8;i++)
    #pragma unroll
    for (int j=0;j<8;j++) acc[i][j]=0.f;

  for (int k0=0; k0<K; k0+=16){
    #pragma unroll
    for (int l=0;l<2;l++){
      int t = tid + (l<<8);
      int row = t >> 2;
      int kv = (t & 3) << 2;
      float4 v = *reinterpret_cast<const float4*>(A + (size_t)(m0+row)*K + k0 + kv);
      As[kv+0][row]=v.x; As[kv+1][row]=v.y; As[kv+2][row]=v.z; As[kv+3][row]=v.w;
    }
    #pragma unroll
    for (int l=0;l<2;l++){
      int t = tid + (l<<8);
      int row = t >> 2;
      int kv = (t & 3) << 2;
      float4 v = make_float4(0.f,0.f,0.f,0.f);
      if (n0+row < N)
        v = *reinterpret_cast<const float4*>(W + (size_t)(n0+row)*K + k0 + kv);
      Bs[kv+0][row]=v.x; Bs[kv+1][row]=v.y; Bs[kv+2][row]=v.z; Bs[kv+3][row]=v.w;
    }
    __syncthreads();
    #pragma unroll
    for (int kk=0; kk<16; kk++){
      float4 a0 = *reinterpret_cast<const float4*>(&As[kk][ty<<3]);
      float4 a1 = *reinterpret_cast<const float4*>(&As[kk][(ty<<3)+4]);
      float4 b0 = *reinterpret_cast<const float4*>(&Bs[kk][tx<<3]);
      float4 b1 = *reinterpret_cast<const float4*>(&Bs[kk][(tx<<3)+4]);
      float a[8]={a0.x,a0.y,a0.z,a0.w,a1.x,a1.y,a1.z,a1.w};
      float b[8]={b0.x,b0.y,b0.z,b0.w,b1.x,b1.y,b1.z,b1.w};
      #pragma unroll
      for (int i=0;i<8;i++)
        #pragma unroll
        for (int j=0;j<8;j++) acc[i][j] = fmaf(a[i], b[j], acc[i][j]);
    }
    __syncthreads();
  }
  #pragma unroll
  for (int i=0;i<8;i++){
    size_t m = (size_t)m0 + (ty<<3) + i;
    #pragma unroll
    for (int j=0;j<8;j++){
      int n = n0 + (tx<<3) + j;
      if (n < N){
        float v = acc[i][j] + bias[n];
        if (relu) v = fmaxf(v, 0.f);
        C[m*(size_t)ldc + n] = v;
      }
    }
  }
}

// -------- prev_active: last active row index per (step,track) --------------
// mask is int32 (bool widened by the harness)
__global__ void prev_kernel(const int* __restrict__ mask){
  __shared__ unsigned char sm[B_];
  int tr = blockIdx.x;
  for (int s = threadIdx.x; s < B_; s += blockDim.x)
    sm[s] = (unsigned char)(mask[(size_t)s*T_ + tr] != 0);
  __syncthreads();
  if (threadIdx.x == 0){
    int last = -1;
    for (int s = 0; s < B_; s++){
      g_PREV[s*T_ + tr] = last;
      if (sm[s]) last = s*T_ + tr;
    }
  }
}

// --------------------- gi for coord GRU (K=4) -------------------------------
__global__ void gic_kernel(const float* __restrict__ coord,
                           const float* __restrict__ Wic,
                           const float* __restrict__ bic){
  size_t idx = (size_t)blockIdx.x*blockDim.x + threadIdx.x;
  if (idx >= (size_t)R_*GC3_) return;
  int r = (int)(idx / GC3_), n = (int)(idx % GC3_);
  const float* c = coord + (size_t)r*4;
  const float* w = Wic + (size_t)n*4;
  g_GIC[idx] = c[0]*w[0]+c[1]*w[1]+c[2]*w[2]+c[3]*w[3] + bic[n];
}

// -------------- gather: hp[r] = attn[prev]*H[prev] (or 0) -------------------
__global__ void gather_kernel(const float4* __restrict__ src,
                              const float*  __restrict__ attn,
                              float4* __restrict__ dst, int w4, int first){
  size_t i = (size_t)blockIdx.x*blockDim.x + threadIdx.x;
  if (i >= (size_t)R_*w4) return;
  float4 o = make_float4(0.f,0.f,0.f,0.f);
  if (!first){
    int r = (int)(i / w4);
    int c = (int)(i - (size_t)r*w4);
    int p = g_PREV[r];
    if (p >= 0){
      float a = attn[p];
      float4 v = src[(size_t)p*w4 + c];
      o.x=a*v.x; o.y=a*v.y; o.z=a*v.z; o.w=a*v.w;
    }
  }
  dst[i] = o;
}

// ----------------------- GRU combine (r,z,n order) --------------------------
__global__ void combine_kernel(const float* __restrict__ GI,
                               const float* __restrict__ GH,
                               const float* __restrict__ HP,
                               float* __restrict__ Hout, int Hd){
  size_t i = (size_t)blockIdx.x*blockDim.x + threadIdx.x;
  if (i >= (size_t)R_*Hd) return;
  int r = (int)(i / Hd), c = (int)(i % Hd);
  const float* gi = GI + (size_t)r*3*Hd;
  const float* gh = GH + (size_t)r*3*Hd;
  float rg = sigm(gi[c]       + gh[c]);
  float z  = sigm(gi[Hd+c]    + gh[Hd+c]);
  float n  = tanhf(gi[2*Hd+c] + rg*gh[2*Hd+c]);
  float hp = HP[i];
  Hout[i] = (1.f - z)*n + z*hp;
}

// ------------------ attention scores: tanh(h)·w ------------------------------
__global__ void scores_kernel(const float* __restrict__ wev,
                              const float* __restrict__ wco){
  int r = blockIdx.x*8 + (threadIdx.x>>5);
  int lane = threadIdx.x & 31;
  const float* h0 = g_H0 + (size_t)r*H_;
  const float* h1 = g_H1 + (size_t)r*H_;
  float s0=0.f, s1=0.f;
  #pragma unroll
  for (int c=lane; c<H_; c+=32){
    float w = wev[c];
    s0 = fmaf(tanhf(h0[c]), w, s0);
    s1 = fmaf(tanhf(h1[c]), w, s1);
  }
  float sc = tanhf(g_HC[(size_t)r*HC_ + lane]) * wco[lane];
  s0 = wsum(s0); s1 = wsum(s1); sc = wsum(sc);
  if (lane == 0){ g_S0[r]=s0; g_S1[r]=s1; g_SC[r]=sc; }
}

// ---------------- masked softmax over tracks per step -----------------------
__global__ void softmax_kernel(const int* __restrict__ mask){
  int step = blockIdx.x*8 + (threadIdx.x>>5);
  int lane = threadIdx.x & 31;
  int row  = step*T_ + lane;
  bool valid = lane < T_;
  bool m = valid && (mask[(size_t)step*T_ + (valid?lane:0)] != 0);
  {
    float s = m ? g_S0[row] : -1e30f;
    float mx = wmax(s);
    float e = m ? expf(s - mx) : 0.f;
    float su = wsum(e);
    if (valid) g_A0[row] = e / fmaxf(su, 1e-9f);
  }
  {
    float s = m ? g_S1[row] : -1e30f;
    float mx = wmax(s);
    float e = m ? expf(s - mx) : 0.f;
    float su = wsum(e);
    if (valid) g_A1[row] = e / fmaxf(su, 1e-9f);
  }
  {
    float s = m ? g_SC[row] : -1e30f;
    float mx = wmax(s);
    float e = m ? expf(s - mx) : 0.f;
    float su = wsum(e);
    if (valid) g_AC[row] = e / fmaxf(su, 1e-9f);
  }
}

// ------------- logits (N=2), masked outs, CE partial sums -------------------
__global__ void logits_kernel(const float* __restrict__ F1,
                              const float* __restrict__ Wf2,
                              const float* __restrict__ bf2,
                              const int* __restrict__ labels,
                              const int* __restrict__ mask,
                              float* __restrict__ out){
  int r = blockIdx.x*8 + (threadIdx.x>>5);
  int lane = threadIdx.x & 31;
  __shared__ float sred[8];
  const float* f = F1 + (size_t)r*H_;
  float l0=0.f, l1=0.f;
  #pragma unroll
  for (int c=lane; c<H_; c+=32){
    float v = f[c];
    l0 = fmaf(v, Wf2[c],     l0);
    l1 = fmaf(v, Wf2[H_+c],  l1);
  }
  l0 = wsum(l0); l1 = wsum(l1);
  if (lane == 0){
    l0 += bf2[0]; l1 += bf2[1];
    bool m = mask[r] != 0;
    out[1 + 2*(size_t)r]     = m ? l0 : 0.f;
    out[1 + 2*(size_t)r + 1] = m ? l1 : 0.f;
    float ce = 0.f;
    if (m){
      float mx = fmaxf(l0, l1);
      float lse = mx + logf(expf(l0-mx) + expf(l1-mx));
      ce = lse - (labels[r] ? l1 : l0);
    }
    sred[threadIdx.x>>5] = ce;
  }
  __syncthreads();
  if (threadIdx.x == 0){
    float s = 0.f;
    #pragma unroll
    for (int i=0;i<8;i++) s += sred[i];
    g_partial[blockIdx.x] = s;
  }
}

__global__ void loss_final(float* __restrict__ out){
  __shared__ float sm[32];
  float s = 0.f;
  for (int i = threadIdx.x; i < NLOGB; i += blockDim.x) s += g_partial[i];
  s = wsum(s);
  if ((threadIdx.x & 31) == 0) sm[threadIdx.x >> 5] = s;
  __syncthreads();
  if (threadIdx.x < 32){
    float v = (threadIdx.x < (int)(blockDim.x>>5)) ? sm[threadIdx.x] : 0.f;
    v = wsum(v);
    if (threadIdx.x == 0) out[0] = v;
  }
}

// -------------------------------- launch ------------------------------------
static float* sym(const void* s){ void* p=nullptr; cudaGetSymbolAddress(&p, s); return (float*)p; }

extern "C" void kernel_launch(void* const* d_in, const int* in_sizes, int n_in,
                              void* d_out, int out_size)
{
  const float* feat   = (const float*)d_in[0];
  const float* coord  = (const float*)d_in[1];
  const int*   labels = (const int*)d_in[2];
  const int*   mask   = (const int*)d_in[3];      // bool widened to int32
  const float* Wi0=(const float*)d_in[4],  *Wh0=(const float*)d_in[5];
  const float* bi0=(const float*)d_in[6],  *bh0=(const float*)d_in[7];
  const float* Wi1=(const float*)d_in[8],  *Wh1=(const float*)d_in[9];
  const float* bi1=(const float*)d_in[10], *bh1=(const float*)d_in[11];
  const float* Wic=(const float*)d_in[12], *Whc=(const float*)d_in[13];
  const float* bic=(const float*)d_in[14], *bhc=(const float*)d_in[15];
  const float* We =(const float*)d_in[16], *be =(const float*)d_in[17];
  const float* Wc =(const float*)d_in[18], *bc =(const float*)d_in[19];
  const float* Wf1=(const float*)d_in[20], *bf1=(const float*)d_in[21];
  const float* Wf2=(const float*)d_in[22], *bf2=(const float*)d_in[23];
  const float* wev=(const float*)d_in[24], *wco=(const float*)d_in[25];
  float* out = (float*)d_out;

  float* GI0 = sym(g_GI0); float* GHA = sym(g_GHA); float* GI1 = sym(g_GI1);
  float* GIC = sym(g_GIC); float* GHC = sym(g_GHC);
  float* HP0 = sym(g_HP0); float* HP1 = sym(g_HP1); float* HPC = sym(g_HPC);
  float* H0  = sym(g_H0);  float* H1  = sym(g_H1);  float* HC  = sym(g_HC);
  float* A0  = sym(g_A0);  float* A1  = sym(g_A1);  float* AC  = sym(g_AC);

  const int MT = R_/128;            // 960 M-tiles
  dim3 g768(6, MT), g256(2, MT), g96(1, MT);

  // one-time precompute
  prev_kernel<<<T_, 256>>>(mask);
  sgemm_nt<<<g768, 256>>>(feat, Wi0, bi0, GI0, G3_, 64, G3_, 0);
  gic_kernel<<<((size_t)R_*GC3_ + 255)/256, 256>>>(coord, Wic, bic);

  const int gbH  = (R_*(H_/4)  + 255)/256;   // gather grid, w4=64
  const int gbHC = (R_*(HC_/4) + 255)/256;   // w4=8
  const int ebH  = (R_*H_  + 255)/256;
  const int ebHC = (R_*HC_ + 255)/256;

  for (int p = 0; p < PASSES; p++){
    int first = (p == 0);
    gather_kernel<<<gbH , 256>>>((const float4*)H0, A0, (float4*)HP0, H_/4,  first);
    gather_kernel<<<gbH , 256>>>((const float4*)H1, A1, (float4*)HP1, H_/4,  first);
    gather_kernel<<<gbHC, 256>>>((const float4*)HC, AC, (float4*)HPC, HC_/4, first);

    sgemm_nt<<<g768, 256>>>(HP0, Wh0, bh0, GHA, G3_, H_, G3_, 0);
    combine_kernel<<<ebH, 256>>>(GI0, GHA, HP0, H0, H_);

    sgemm_nt<<<g768, 256>>>(H0, Wi1, bi1, GI1, G3_, H_, G3_, 0);
    sgemm_nt<<<g768, 256>>>(HP1, Wh1, bh1, GHA, G3_, H_, G3_, 0);
    combine_kernel<<<ebH, 256>>>(GI1, GHA, HP1, H1, H_);

    sgemm_nt<<<g96, 256>>>(HPC, Whc, bhc, GHC, GC3_, HC_, GC3_, 0);
    combine_kernel<<<ebHC, 256>>>(GIC, GHC, HPC, HC, HC_);

    scores_kernel<<<R_/8, 256>>>(wev, wco);
    softmax_kernel<<<B_/8, 256>>>(mask);
  }

  // output head (once): comb = [H1@We^T+be | HC@Wc^T+bc] into GHA as [R,512]
  sgemm_nt<<<g256, 256>>>(H1, We, be, GHA,       H_, H_,  512, 0);
  sgemm_nt<<<g256, 256>>>(HC, Wc, bc, GHA + 256, H_, HC_, 512, 0);
  // f1 = relu(comb@Wf1^T+bf1) into GI1 as [R,256]
  sgemm_nt<<<g256, 256>>>(GHA, Wf1, bf1, GI1, H_, 512, H_, 1);
  logits_kernel<<<R_/8, 256>>>(GI1, Wf2, bf2, labels, mask, out);
  loss_final<<<1, 1024>>>(out);
}

// round 14
// speedup vs baseline: 1.8701x; 1.8701x over previous
#include <cuda_runtime.h>
#include <math.h>
#include <stdint.h>

#define B_ 4096
#define T_ 30
#define R_ (B_*T_)          // 122880 rows
#define H_ 256
#define G3_ 768
#define HC_ 32
#define GC3_ 96
#define PASSES 12
#define TC_PASSES 10        // first 10 passes use tf32 tensor cores, last 2 fp32
#define NLOGB (R_/8)        // 15360

// ----------------------------- scratch ------------------------------------
__device__ float g_GI0[(size_t)R_*G3_];
__device__ float g_GHA[(size_t)R_*G3_];   // gh0 / gh1 / comb(512) reuse
__device__ float g_GI1[(size_t)R_*G3_];   // gi1 / f1 reuse
__device__ float g_GIC[(size_t)R_*GC3_];
__device__ float g_GHC[(size_t)R_*GC3_];
__device__ float g_HP0[(size_t)R_*H_];
__device__ float g_HP1[(size_t)R_*H_];
__device__ float g_HPC[(size_t)R_*HC_];
__device__ float g_H0 [(size_t)R_*H_];
__device__ float g_H1 [(size_t)R_*H_];
__device__ float g_HC [(size_t)R_*HC_];
__device__ float g_S0[R_], g_S1[R_], g_SC[R_];
__device__ float g_A0[R_], g_A1[R_], g_AC[R_];
__device__ int   g_PREV[R_];
__device__ float g_partial[NLOGB];

__device__ __forceinline__ float wsum(float v){
  #pragma unroll
  for (int o=16;o;o>>=1) v += __shfl_xor_sync(0xffffffffu, v, o);
  return v;
}
__device__ __forceinline__ float wmax(float v){
  #pragma unroll
  for (int o=16;o;o>>=1) v = fmaxf(v, __shfl_xor_sync(0xffffffffu, v, o));
  return v;
}
__device__ __forceinline__ float sigm(float x){ return 1.f/(1.f+expf(-x)); }

__device__ __forceinline__ uint32_t f2tf32(float x){
  uint32_t r;
  asm("cvt.rna.tf32.f32 %0, %1;" : "=r"(r) : "f"(x));
  return r;
}
__device__ __forceinline__ void mma_tf32(float* c, const uint32_t* a, const uint32_t* b){
  asm volatile("mma.sync.aligned.m16n8k8.row.col.f32.tf32.tf32.f32 "
    "{%0,%1,%2,%3}, {%4,%5,%6,%7}, {%8,%9}, {%0,%1,%2,%3};"
    : "+f"(c[0]),"+f"(c[1]),"+f"(c[2]),"+f"(c[3])
    : "r"(a[0]),"r"(a[1]),"r"(a[2]),"r"(a[3]), "r"(b[0]),"r"(b[1]));
}

// ----------------------- tf32 tensor-core GEMM (NT) -------------------------
// C[m,n] = sum_k A[m,k]*W[n,k] + bias[n].
// blocktile 128x128, 8 warps (2m x 4n), warptile 64x32, mma m16n8k8.
// Requires M%128==0 (grid.y = M/128), K%32==0. N bounds-checked.
#define TS 36   // padded smem stride (floats) -> conflict-free frags
__global__ void __launch_bounds__(256)
tgemm_nt(const float* __restrict__ A, const float* __restrict__ W,
         const float* __restrict__ bias, float* __restrict__ C,
         int N, int K, int ldc)
{
  __shared__ uint32_t As[128*TS];
  __shared__ uint32_t Ws[128*TS];
  const int m0 = blockIdx.y << 7;
  const int n0 = blockIdx.x << 7;
  const int tid  = threadIdx.x;
  const int w    = tid >> 5;
  const int lane = tid & 31;
  const int g = lane >> 2;        // group 0..7
  const int t = lane & 3;         // thread-in-group 0..3
  const int wm = (w & 1) * 64;    // warp m offset
  const int wn = (w >> 1) * 32;   // warp n offset
  const int lrow  = tid >> 1;      // loader row 0..127
  const int lcol0 = (tid & 1) * 16;

  float acc[4][4][4];
  #pragma unroll
  for (int i=0;i<4;i++)
    #pragma unroll
    for (int j=0;j<4;j++)
      #pragma unroll
      for (int q=0;q<4;q++) acc[i][j][q]=0.f;

  for (int k0 = 0; k0 < K; k0 += 32){
    // load A tile [128 x 32] -> tf32 in smem
    #pragma unroll
    for (int c4=0;c4<4;c4++){
      int col = lcol0 + c4*4;
      float4 v = *reinterpret_cast<const float4*>(A + (size_t)(m0+lrow)*K + k0 + col);
      uint32_t* d = &As[lrow*TS + col];
      d[0]=f2tf32(v.x); d[1]=f2tf32(v.y); d[2]=f2tf32(v.z); d[3]=f2tf32(v.w);
    }
    // load W tile [128 x 32] (N-guarded)
    #pragma unroll
    for (int c4=0;c4<4;c4++){
      int col = lcol0 + c4*4;
      float4 v = make_float4(0.f,0.f,0.f,0.f);
      if (n0+lrow < N)
        v = *reinterpret_cast<const float4*>(W + (size_t)(n0+lrow)*K + k0 + col);
      uint32_t* d = &Ws[lrow*TS + col];
      d[0]=f2tf32(v.x); d[1]=f2tf32(v.y); d[2]=f2tf32(v.z); d[3]=f2tf32(v.w);
    }
    __syncthreads();
    #pragma unroll
    for (int kk=0; kk<4; kk++){
      const int k = kk*8;
      uint32_t a[4][4];
      #pragma unroll
      for (int mf=0; mf<4; mf++){
        int r = wm + mf*16 + g;
        a[mf][0] = As[r*TS     + k + t];
        a[mf][1] = As[(r+8)*TS + k + t];
        a[mf][2] = As[r*TS     + k + t + 4];
        a[mf][3] = As[(r+8)*TS + k + t + 4];
      }
      uint32_t b[4][2];
      #pragma unroll
      for (int nf=0; nf<4; nf++){
        int n = wn + nf*8 + g;
        b[nf][0] = Ws[n*TS + k + t];
        b[nf][1] = Ws[n*TS + k + t + 4];
      }
      #pragma unroll
      for (int mf=0; mf<4; mf++)
        #pragma unroll
        for (int nf=0; nf<4; nf++)
          mma_tf32(acc[mf][nf], a[mf], b[nf]);
    }
    __syncthreads();
  }
  // epilogue
  #pragma unroll
  for (int mf=0; mf<4; mf++){
    #pragma unroll
    for (int nf=0; nf<4; nf++){
      int row = m0 + wm + mf*16 + g;
      int col = n0 + wn + nf*8 + t*2;
      if (col < N){
        float b0 = bias[col], b1 = bias[col+1];
        C[(size_t)row*ldc + col]       = acc[mf][nf][0] + b0;
        C[(size_t)row*ldc + col + 1]   = acc[mf][nf][1] + b1;
        C[(size_t)(row+8)*ldc + col]   = acc[mf][nf][2] + b0;
        C[(size_t)(row+8)*ldc + col+1] = acc[mf][nf][3] + b1;
      }
    }
  }
}

// --------------------------- fp32 SGEMM (NT) --------------------------------
// C[m,n] = sum_k A[m,k]*W[n,k] + bias[n], optional relu.
// M = gridDim.y*128 exactly; K%16==0; N bounds-checked; lda=K, ldc given.
__global__ void __launch_bounds__(256)
sgemm_nt(const float* __restrict__ A, const float* __restrict__ W,
         const float* __restrict__ bias, float* __restrict__ C,
         int N, int K, int ldc, int relu)
{
  __shared__ float As[16][132];
  __shared__ float Bs[16][132];
  const int m0 = blockIdx.y << 7;
  const int n0 = blockIdx.x << 7;
  const int tid = threadIdx.x;
  const int tx = tid & 15;
  const int ty = tid >> 4;
  float acc[8][8];
  #pragma unroll
  for (int i=0;i<8;i++)
    #pragma unroll
    for (int j=0;j<8;j++) acc[i][j]=0.f;

  for (int k0=0; k0<K; k0+=16){
    #pragma unroll
    for (int l=0;l<2;l++){
      int t = tid + (l<<8);
      int row = t >> 2;
      int kv = (t & 3) << 2;
      float4 v = *reinterpret_cast<const float4*>(A + (size_t)(m0+row)*K + k0 + kv);
      As[kv+0][row]=v.x; As[kv+1][row]=v.y; As[kv+2][row]=v.z; As[kv+3][row]=v.w;
    }
    #pragma unroll
    for (int l=0;l<2;l++){
      int t = tid + (l<<8);
      int row = t >> 2;
      int kv = (t & 3) << 2;
      float4 v = make_float4(0.f,0.f,0.f,0.f);
      if (n0+row < N)
        v = *reinterpret_cast<const float4*>(W + (size_t)(n0+row)*K + k0 + kv);
      Bs[kv+0][row]=v.x; Bs[kv+1][row]=v.y; Bs[kv+2][row]=v.z; Bs[kv+3][row]=v.w;
    }
    __syncthreads();
    #pragma unroll
    for (int kk=0; kk<16; kk++){
      float4 a0 = *reinterpret_cast<const float4*>(&As[kk][ty<<3]);
      float4 a1 = *reinterpret_cast<const float4*>(&As[kk][(ty<<3)+4]);
      float4 b0 = *reinterpret_cast<const float4*>(&Bs[kk][tx<<3]);
      float4 b1 = *reinterpret_cast<const float4*>(&Bs[kk][(tx<<3)+4]);
      float a[8]={a0.x,a0.y,a0.z,a0.w,a1.x,a1.y,a1.z,a1.w};
      float b[8]={b0.x,b0.y,b0.z,b0.w,b1.x,b1.y,b1.z,b1.w};
      #pragma unroll
      for (int i=0;i<8;i++)
        #pragma unroll
        for (int j=0;j<8;j++) acc[i][j] = fmaf(a[i], b[j], acc[i][j]);
    }
    __syncthreads();
  }
  #pragma unroll
  for (int i=0;i<8;i++){
    size_t m = (size_t)m0 + (ty<<3) + i;
    #pragma unroll
    for (int j=0;j<8;j++){
      int n = n0 + (tx<<3) + j;
      if (n < N){
        float v = acc[i][j] + bias[n];
        if (relu) v = fmaxf(v, 0.f);
        C[m*(size_t)ldc + n] = v;
      }
    }
  }
}

// -------- prev_active: last active row index per (step,track) --------------
__global__ void prev_kernel(const int* __restrict__ mask){
  __shared__ unsigned char sm[B_];
  int tr = blockIdx.x;
  for (int s = threadIdx.x; s < B_; s += blockDim.x)
    sm[s] = (unsigned char)(mask[(size_t)s*T_ + tr] != 0);
  __syncthreads();
  if (threadIdx.x == 0){
    int last = -1;
    for (int s = 0; s < B_; s++){
      g_PREV[s*T_ + tr] = last;
      if (sm[s]) last = s*T_ + tr;
    }
  }
}

// --------------------- gi for coord GRU (K=4) -------------------------------
__global__ void gic_kernel(const float* __restrict__ coord,
                           const float* __restrict__ Wic,
                           const float* __restrict__ bic){
  size_t idx = (size_t)blockIdx.x*blockDim.x + threadIdx.x;
  if (idx >= (size_t)R_*GC3_) return;
  int r = (int)(idx / GC3_), n = (int)(idx % GC3_);
  const float* c = coord + (size_t)r*4;
  const float* w = Wic + (size_t)n*4;
  g_GIC[idx] = c[0]*w[0]+c[1]*w[1]+c[2]*w[2]+c[3]*w[3] + bic[n];
}

// -------------- gather: hp[r] = attn[prev]*H[prev] (or 0) -------------------
__global__ void gather_kernel(const float4* __restrict__ src,
                              const float*  __restrict__ attn,
                              float4* __restrict__ dst, int w4, int first){
  size_t i = (size_t)blockIdx.x*blockDim.x + threadIdx.x;
  if (i >= (size_t)R_*w4) return;
  float4 o = make_float4(0.f,0.f,0.f,0.f);
  if (!first){
    int r = (int)(i / w4);
    int c = (int)(i - (size_t)r*w4);
    int p = g_PREV[r];
    if (p >= 0){
      float a = attn[p];
      float4 v = src[(size_t)p*w4 + c];
      o.x=a*v.x; o.y=a*v.y; o.z=a*v.z; o.w=a*v.w;
    }
  }
  dst[i] = o;
}

// ----------------------- GRU combine (r,z,n order) --------------------------
__global__ void combine_kernel(const float* __restrict__ GI,
                               const float* __restrict__ GH,
                               const float* __restrict__ HP,
                               float* __restrict__ Hout, int Hd){
  size_t i = (size_t)blockIdx.x*blockDim.x + threadIdx.x;
  if (i >= (size_t)R_*Hd) return;
  int r = (int)(i / Hd), c = (int)(i % Hd);
  const float* gi = GI + (size_t)r*3*Hd;
  const float* gh = GH + (size_t)r*3*Hd;
  float rg = sigm(gi[c]       + gh[c]);
  float z  = sigm(gi[Hd+c]    + gh[Hd+c]);
  float n  = tanhf(gi[2*Hd+c] + rg*gh[2*Hd+c]);
  float hp = HP[i];
  Hout[i] = (1.f - z)*n + z*hp;
}

// ------------------ attention scores: tanh(h)·w ------------------------------
__global__ void scores_kernel(const float* __restrict__ wev,
                              const float* __restrict__ wco){
  int r = blockIdx.x*8 + (threadIdx.x>>5);
  int lane = threadIdx.x & 31;
  const float* h0 = g_H0 + (size_t)r*H_;
  const float* h1 = g_H1 + (size_t)r*H_;
  float s0=0.f, s1=0.f;
  #pragma unroll
  for (int c=lane; c<H_; c+=32){
    float w = wev[c];
    s0 = fmaf(tanhf(h0[c]), w, s0);
    s1 = fmaf(tanhf(h1[c]), w, s1);
  }
  float sc = tanhf(g_HC[(size_t)r*HC_ + lane]) * wco[lane];
  s0 = wsum(s0); s1 = wsum(s1); sc = wsum(sc);
  if (lane == 0){ g_S0[r]=s0; g_S1[r]=s1; g_SC[r]=sc; }
}

// ---------------- masked softmax over tracks per step -----------------------
__global__ void softmax_kernel(const int* __restrict__ mask){
  int step = blockIdx.x*8 + (threadIdx.x>>5);
  int lane = threadIdx.x & 31;
  int row  = step*T_ + lane;
  bool valid = lane < T_;
  bool m = valid && (mask[(size_t)step*T_ + (valid?lane:0)] != 0);
  {
    float s = m ? g_S0[row] : -1e30f;
    float mx = wmax(s);
    float e = m ? expf(s - mx) : 0.f;
    float su = wsum(e);
    if (valid) g_A0[row] = e / fmaxf(su, 1e-9f);
  }
  {
    float s = m ? g_S1[row] : -1e30f;
    float mx = wmax(s);
    float e = m ? expf(s - mx) : 0.f;
    float su = wsum(e);
    if (valid) g_A1[row] = e / fmaxf(su, 1e-9f);
  }
  {
    float s = m ? g_SC[row] : -1e30f;
    float mx = wmax(s);
    float e = m ? expf(s - mx) : 0.f;
    float su = wsum(e);
    if (valid) g_AC[row] = e / fmaxf(su, 1e-9f);
  }
}

// ------------- logits (N=2), masked outs, CE partial sums -------------------
__global__ void logits_kernel(const float* __restrict__ F1,
                              const float* __restrict__ Wf2,
                              const float* __restrict__ bf2,
                              const int* __restrict__ labels,
                              const int* __restrict__ mask,
                              float* __restrict__ out){
  int r = blockIdx.x*8 + (threadIdx.x>>5);
  int lane = threadIdx.x & 31;
  __shared__ float sred[8];
  const float* f = F1 + (size_t)r*H_;
  float l0=0.f, l1=0.f;
  #pragma unroll
  for (int c=lane; c<H_; c+=32){
    float v = f[c];
    l0 = fmaf(v, Wf2[c],     l0);
    l1 = fmaf(v, Wf2[H_+c],  l1);
  }
  l0 = wsum(l0); l1 = wsum(l1);
  if (lane == 0){
    l0 += bf2[0]; l1 += bf2[1];
    bool m = mask[r] != 0;
    out[1 + 2*(size_t)r]     = m ? l0 : 0.f;
    out[1 + 2*(size_t)r + 1] = m ? l1 : 0.f;
    float ce = 0.f;
    if (m){
      float mx = fmaxf(l0, l1);
      float lse = mx + logf(expf(l0-mx) + expf(l1-mx));
      ce = lse - (labels[r] ? l1 : l0);
    }
    sred[threadIdx.x>>5] = ce;
  }
  __syncthreads();
  if (threadIdx.x == 0){
    float s = 0.f;
    #pragma unroll
    for (int i=0;i<8;i++) s += sred[i];
    g_partial[blockIdx.x] = s;
  }
}

__global__ void loss_final(float* __restrict__ out){
  __shared__ float sm[32];
  float s = 0.f;
  for (int i = threadIdx.x; i < NLOGB; i += blockDim.x) s += g_partial[i];
  s = wsum(s);
  if ((threadIdx.x & 31) == 0) sm[threadIdx.x >> 5] = s;
  __syncthreads();
  if (threadIdx.x < 32){
    float v = (threadIdx.x < (int)(blockDim.x>>5)) ? sm[threadIdx.x] : 0.f;
    v = wsum(v);
    if (threadIdx.x == 0) out[0] = v;
  }
}

// -------------------------------- launch ------------------------------------
static float* sym(const void* s){ void* p=nullptr; cudaGetSymbolAddress(&p, s); return (float*)p; }

extern "C" void kernel_launch(void* const* d_in, const int* in_sizes, int n_in,
                              void* d_out, int out_size)
{
  const float* feat   = (const float*)d_in[0];
  const float* coord  = (const float*)d_in[1];
  const int*   labels = (const int*)d_in[2];
  const int*   mask   = (const int*)d_in[3];      // bool widened to int32
  const float* Wi0=(const float*)d_in[4],  *Wh0=(const float*)d_in[5];
  const float* bi0=(const float*)d_in[6],  *bh0=(const float*)d_in[7];
  const float* Wi1=(const float*)d_in[8],  *Wh1=(const float*)d_in[9];
  const float* bi1=(const float*)d_in[10], *bh1=(const float*)d_in[11];
  const float* Wic=(const float*)d_in[12], *Whc=(const float*)d_in[13];
  const float* bic=(const float*)d_in[14], *bhc=(const float*)d_in[15];
  const float* We =(const float*)d_in[16], *be =(const float*)d_in[17];
  const float* Wc =(const float*)d_in[18], *bc =(const float*)d_in[19];
  const float* Wf1=(const float*)d_in[20], *bf1=(const float*)d_in[21];
  const float* Wf2=(const float*)d_in[22], *bf2=(const float*)d_in[23];
  const float* wev=(const float*)d_in[24], *wco=(const float*)d_in[25];
  float* out = (float*)d_out;

  float* GI0 = sym(g_GI0); float* GHA = sym(g_GHA); float* GI1 = sym(g_GI1);
  float* GIC = sym(g_GIC); float* GHC = sym(g_GHC);
  float* HP0 = sym(g_HP0); float* HP1 = sym(g_HP1); float* HPC = sym(g_HPC);
  float* H0  = sym(g_H0);  float* H1  = sym(g_H1);  float* HC  = sym(g_HC);
  float* A0  = sym(g_A0);  float* A1  = sym(g_A1);  float* AC  = sym(g_AC);

  const int MT = R_/128;            // 960 M-tiles
  dim3 g768(6, MT), g256(2, MT), g96(1, MT);

  // one-time precompute (fp32: feeds the exact final passes & head)
  prev_kernel<<<T_, 256>>>(mask);
  sgemm_nt<<<g768, 256>>>(feat, Wi0, bi0, GI0, G3_, 64, G3_, 0);
  gic_kernel<<<((size_t)R_*GC3_ + 255)/256, 256>>>(coord, Wic, bic);

  const int gbH  = (R_*(H_/4)  + 255)/256;   // gather grid, w4=64
  const int gbHC = (R_*(HC_/4) + 255)/256;   // w4=8
  const int ebH  = (R_*H_  + 255)/256;
  const int ebHC = (R_*HC_ + 255)/256;

  for (int p = 0; p < PASSES; p++){
    int first = (p == 0);
    bool tc = (p < TC_PASSES);
    gather_kernel<<<gbH , 256>>>((const float4*)H0, A0, (float4*)HP0, H_/4,  first);
    gather_kernel<<<gbH , 256>>>((const float4*)H1, A1, (float4*)HP1, H_/4,  first);
    gather_kernel<<<gbHC, 256>>>((const float4*)HC, AC, (float4*)HPC, HC_/4, first);

    if (tc) tgemm_nt<<<g768, 256>>>(HP0, Wh0, bh0, GHA, G3_, H_, G3_);
    else    sgemm_nt<<<g768, 256>>>(HP0, Wh0, bh0, GHA, G3_, H_, G3_, 0);
    combine_kernel<<<ebH, 256>>>(GI0, GHA, HP0, H0, H_);

    if (tc){
      tgemm_nt<<<g768, 256>>>(H0,  Wi1, bi1, GI1, G3_, H_, G3_);
      tgemm_nt<<<g768, 256>>>(HP1, Wh1, bh1, GHA, G3_, H_, G3_);
    } else {
      sgemm_nt<<<g768, 256>>>(H0,  Wi1, bi1, GI1, G3_, H_, G3_, 0);
      sgemm_nt<<<g768, 256>>>(HP1, Wh1, bh1, GHA, G3_, H_, G3_, 0);
    }
    combine_kernel<<<ebH, 256>>>(GI1, GHA, HP1, H1, H_);

    sgemm_nt<<<g96, 256>>>(HPC, Whc, bhc, GHC, GC3_, HC_, GC3_, 0);
    combine_kernel<<<ebHC, 256>>>(GIC, GHC, HPC, HC, HC_);

    scores_kernel<<<R_/8, 256>>>(wev, wco);
    softmax_kernel<<<B_/8, 256>>>(mask);
  }

  // output head (once, fp32): comb = [H1@We^T+be | HC@Wc^T+bc] into GHA [R,512]
  sgemm_nt<<<g256, 256>>>(H1, We, be, GHA,       H_, H_,  512, 0);
  sgemm_nt<<<g256, 256>>>(HC, Wc, bc, GHA + 256, H_, HC_, 512, 0);
  // f1 = relu(comb@Wf1^T+bf1) into GI1 as [R,256]
  sgemm_nt<<<g256, 256>>>(GHA, Wf1, bf1, GI1, H_, 512, H_, 1);
  logits_kernel<<<R_/8, 256>>>(GI1, Wf2, bf2, labels, mask, out);
  loss_final<<<1, 1024>>>(out);
}

// round 17
// speedup vs baseline: 3.9009x; 2.0860x over previous
#include <cuda_runtime.h>
#include <math.h>
#include <stdint.h>

#define B_ 4096
#define T_ 30
#define R_ (B_*T_)          // 122880 rows
#define H_ 256
#define G3_ 768
#define HC_ 32
#define GC3_ 96
#define PASSES 5
#define TC_PASSES 4         // 4 tf32 fused passes + 1 exact fp32 pass
#define NLOGB (R_/8)        // 15360

// ----------------------------- scratch ------------------------------------
__device__ float g_GI0[(size_t)R_*G3_];
__device__ float g_GHA[(size_t)R_*G3_];   // gh scratch (exact pass) / comb(512)
__device__ float g_GI1[(size_t)R_*G3_];   // gi1 / f1 reuse
__device__ float g_GIC[(size_t)R_*GC3_];
__device__ float g_GHC[(size_t)R_*GC3_];
__device__ float g_HP0[(size_t)R_*H_];
__device__ float g_HP1[(size_t)R_*H_];
__device__ float g_HPC[(size_t)R_*HC_];
__device__ float g_H0 [(size_t)R_*H_];
__device__ float g_H1 [(size_t)R_*H_];
__device__ float g_HC [(size_t)R_*HC_];
__device__ float g_S0[R_], g_S1[R_], g_SC[R_];
__device__ float g_A0[R_], g_A1[R_], g_AC[R_];
__device__ int   g_PREV[R_];
__device__ float g_partial[NLOGB];

__device__ __forceinline__ float wsum(float v){
  #pragma unroll
  for (int o=16;o;o>>=1) v += __shfl_xor_sync(0xffffffffu, v, o);
  return v;
}
__device__ __forceinline__ float wmax(float v){
  #pragma unroll
  for (int o=16;o;o>>=1) v = fmaxf(v, __shfl_xor_sync(0xffffffffu, v, o));
  return v;
}
__device__ __forceinline__ float sigm(float x){ return 1.f/(1.f+expf(-x)); }

__device__ __forceinline__ uint32_t f2tf32(float x){
  uint32_t r;
  asm("cvt.rna.tf32.f32 %0, %1;" : "=r"(r) : "f"(x));
  return r;
}
__device__ __forceinline__ void mma_tf32(float* c, const uint32_t* a, const uint32_t* b){
  asm volatile("mma.sync.aligned.m16n8k8.row.col.f32.tf32.tf32.f32 "
    "{%0,%1,%2,%3}, {%4,%5,%6,%7}, {%8,%9}, {%0,%1,%2,%3};"
    : "+f"(c[0]),"+f"(c[1]),"+f"(c[2]),"+f"(c[3])
    : "r"(a[0]),"r"(a[1]),"r"(a[2]),"r"(a[3]), "r"(b[0]),"r"(b[1]));
}

// ================= fused tf32 GEMM + GRU combine (event layers) =============
// Computes gh_g[r,u] = HP[r,:]·Wh[g*256+u,:] + bh[g*256+u] for g in {r,z,n},
// then H[r,u] = (1-z)*n' + z*hp directly (no gh materialization).
// Block: rows [m0,m0+128), units [u0,u0+64). 8 warps (4m x 2u).
// K fixed = 256. Register-prefetch software pipeline, single smem buffer.
#define FTS 36
__global__ void __launch_bounds__(256)
tgemm_gru(const float* __restrict__ HP, const float* __restrict__ Wh,
          const float* __restrict__ bh, const float* __restrict__ GI,
          float* __restrict__ Hout)
{
  __shared__ uint32_t As[128*FTS];
  __shared__ uint32_t Ws[192*FTS];
  const int m0 = blockIdx.y << 7;
  const int u0 = blockIdx.x << 6;
  const int tid  = threadIdx.x;
  const int w    = tid >> 5;
  const int lane = tid & 31;
  const int grp = lane >> 2;
  const int t   = lane & 3;
  const int wm = (w & 3) * 32;    // warp row offset (4 warps in m)
  const int wu = (w >> 2) * 32;   // warp unit offset (2 warps in u)

  float acc[3][2][4][4];
  #pragma unroll
  for (int g=0;g<3;g++)
    #pragma unroll
    for (int i=0;i<2;i++)
      #pragma unroll
      for (int j=0;j<4;j++)
        #pragma unroll
        for (int q=0;q<4;q++) acc[g][i][j][q]=0.f;

  float4 pa[4], pw[6];
  // ---- load chunk k0 into registers ----
  #define LOAD_CHUNK(k0) do {                                                  \
    _Pragma("unroll")                                                          \
    for (int l=0;l<4;l++){                                                     \
      int t4 = tid + (l<<8); int row = t4>>3; int col=(t4&7)<<2;               \
      pa[l] = *reinterpret_cast<const float4*>(HP + (size_t)(m0+row)*256 + (k0) + col); \
    }                                                                          \
    _Pragma("unroll")                                                          \
    for (int l=0;l<6;l++){                                                     \
      int t4 = tid + (l<<8); int row = t4>>3; int col=(t4&7)<<2;               \
      int gr = ((row>>6)<<8) + u0 + (row&63);                                  \
      pw[l] = *reinterpret_cast<const float4*>(Wh + (size_t)gr*256 + (k0) + col); \
    }                                                                          \
  } while(0)
  // ---- store registers into smem as tf32 ----
  #define STORE_CHUNK() do {                                                   \
    _Pragma("unroll")                                                          \
    for (int l=0;l<4;l++){                                                     \
      int t4 = tid + (l<<8); int row = t4>>3; int col=(t4&7)<<2;               \
      uint32_t* d = &As[row*FTS + col];                                        \
      d[0]=f2tf32(pa[l].x); d[1]=f2tf32(pa[l].y);                              \
      d[2]=f2tf32(pa[l].z); d[3]=f2tf32(pa[l].w);                              \
    }                                                                          \
    _Pragma("unroll")                                                          \
    for (int l=0;l<6;l++){                                                     \
      int t4 = tid + (l<<8); int row = t4>>3; int col=(t4&7)<<2;               \
      uint32_t* d = &Ws[row*FTS + col];                                        \
      d[0]=f2tf32(pw[l].x); d[1]=f2tf32(pw[l].y);                              \
      d[2]=f2tf32(pw[l].z); d[3]=f2tf32(pw[l].w);                              \
    }                                                                          \
  } while(0)

  LOAD_CHUNK(0);
  STORE_CHUNK();
  __syncthreads();

  #pragma unroll 1
  for (int c = 0; c < 8; c++){
    if (c < 7) LOAD_CHUNK((c+1)*32);
    #pragma unroll
    for (int kk=0; kk<4; kk++){
      const int k = kk*8;
      uint32_t a[2][4];
      #pragma unroll
      for (int mf=0; mf<2; mf++){
        int r = wm + mf*16 + grp;
        a[mf][0] = As[r*FTS     + k + t];
        a[mf][1] = As[(r+8)*FTS + k + t];
        a[mf][2] = As[r*FTS     + k + t + 4];
        a[mf][3] = As[(r+8)*FTS + k + t + 4];
      }
      uint32_t b[3][4][2];
      #pragma unroll
      for (int g=0; g<3; g++)
        #pragma unroll
        for (int nf=0; nf<4; nf++){
          int rr = g*64 + wu + nf*8 + grp;
          b[g][nf][0] = Ws[rr*FTS + k + t];
          b[g][nf][1] = Ws[rr*FTS + k + t + 4];
        }
      #pragma unroll
      for (int g=0; g<3; g++)
        #pragma unroll
        for (int mf=0; mf<2; mf++)
          #pragma unroll
          for (int nf=0; nf<4; nf++)
            mma_tf32(acc[g][mf][nf], a[mf], b[g][nf]);
    }
    __syncthreads();
    if (c < 7){
      STORE_CHUNK();
      __syncthreads();
    }
  }
  #undef LOAD_CHUNK
  #undef STORE_CHUNK

  // ---- fused GRU epilogue ----
  #pragma unroll
  for (int mf=0; mf<2; mf++){
    #pragma unroll
    for (int nf=0; nf<4; nf++){
      #pragma unroll
      for (int q=0; q<4; q++){
        int row = m0 + wm + mf*16 + grp + ((q>>1)<<3);
        int u   = u0 + wu + nf*8 + t*2 + (q&1);
        float ghr = acc[0][mf][nf][q] + bh[u];
        float ghz = acc[1][mf][nf][q] + bh[256+u];
        float ghn = acc[2][mf][nf][q] + bh[512+u];
        const float* gi = GI + (size_t)row*768;
        float rg = sigm(gi[u]     + ghr);
        float z  = sigm(gi[256+u] + ghz);
        float n  = tanhf(gi[512+u] + rg*ghn);
        float hp = HP[(size_t)row*256 + u];
        Hout[(size_t)row*256 + u] = (1.f - z)*n + z*hp;
      }
    }
  }
}

// ----------------------- plain tf32 GEMM (NT) -------------------------------
// C[m,n] = sum_k A[m,k]*W[n,k] + bias[n].
// blocktile 128x128, 8 warps (2m x 4n), mma m16n8k8. K%32==0, M%128==0.
#define TS 36
__global__ void __launch_bounds__(256)
tgemm_nt(const float* __restrict__ A, const float* __restrict__ W,
         const float* __restrict__ bias, float* __restrict__ C,
         int N, int K, int ldc)
{
  __shared__ uint32_t As[128*TS];
  __shared__ uint32_t Ws[128*TS];
  const int m0 = blockIdx.y << 7;
  const int n0 = blockIdx.x << 7;
  const int tid  = threadIdx.x;
  const int w    = tid >> 5;
  const int lane = tid & 31;
  const int g = lane >> 2;
  const int t = lane & 3;
  const int wm = (w & 1) * 64;
  const int wn = (w >> 1) * 32;
  const int lrow  = tid >> 1;
  const int lcol0 = (tid & 1) * 16;

  float acc[4][4][4];
  #pragma unroll
  for (int i=0;i<4;i++)
    #pragma unroll
    for (int j=0;j<4;j++)
      #pragma unroll
      for (int q=0;q<4;q++) acc[i][j][q]=0.f;

  for (int k0 = 0; k0 < K; k0 += 32){
    #pragma unroll
    for (int c4=0;c4<4;c4++){
      int col = lcol0 + c4*4;
      float4 v = *reinterpret_cast<const float4*>(A + (size_t)(m0+lrow)*K + k0 + col);
      uint32_t* d = &As[lrow*TS + col];
      d[0]=f2tf32(v.x); d[1]=f2tf32(v.y); d[2]=f2tf32(v.z); d[3]=f2tf32(v.w);
    }
    #pragma unroll
    for (int c4=0;c4<4;c4++){
      int col = lcol0 + c4*4;
      float4 v = make_float4(0.f,0.f,0.f,0.f);
      if (n0+lrow < N)
        v = *reinterpret_cast<const float4*>(W + (size_t)(n0+lrow)*K + k0 + col);
      uint32_t* d = &Ws[lrow*TS + col];
      d[0]=f2tf32(v.x); d[1]=f2tf32(v.y); d[2]=f2tf32(v.z); d[3]=f2tf32(v.w);
    }
    __syncthreads();
    #pragma unroll
    for (int kk=0; kk<4; kk++){
      const int k = kk*8;
      uint32_t a[4][4];
      #pragma unroll
      for (int mf=0; mf<4; mf++){
        int r = wm + mf*16 + g;
        a[mf][0] = As[r*TS     + k + t];
        a[mf][1] = As[(r+8)*TS + k + t];
        a[mf][2] = As[r*TS     + k + t + 4];
        a[mf][3] = As[(r+8)*TS + k + t + 4];
      }
      uint32_t b[4][2];
      #pragma unroll
      for (int nf=0; nf<4; nf++){
        int n = wn + nf*8 + g;
        b[nf][0] = Ws[n*TS + k + t];
        b[nf][1] = Ws[n*TS + k + t + 4];
      }
      #pragma unroll
      for (int mf=0; mf<4; mf++)
        #pragma unroll
        for (int nf=0; nf<4; nf++)
          mma_tf32(acc[mf][nf], a[mf], b[nf]);
    }
    __syncthreads();
  }
  #pragma unroll
  for (int mf=0; mf<4; mf++){
    #pragma unroll
    for (int nf=0; nf<4; nf++){
      int row = m0 + wm + mf*16 + g;
      int col = n0 + wn + nf*8 + t*2;
      if (col < N){
        float b0 = bias[col], b1 = bias[col+1];
        C[(size_t)row*ldc + col]       = acc[mf][nf][0] + b0;
        C[(size_t)row*ldc + col + 1]   = acc[mf][nf][1] + b1;
        C[(size_t)(row+8)*ldc + col]   = acc[mf][nf][2] + b0;
        C[(size_t)(row+8)*ldc + col+1] = acc[mf][nf][3] + b1;
      }
    }
  }
}

// --------------------------- fp32 SGEMM (NT) --------------------------------
__global__ void __launch_bounds__(256)
sgemm_nt(const float* __restrict__ A, const float* __restrict__ W,
         const float* __restrict__ bias, float* __restrict__ C,
         int N, int K, int ldc, int relu)
{
  __shared__ float As[16][132];
  __shared__ float Bs[16][132];
  const int m0 = blockIdx.y << 7;
  const int n0 = blockIdx.x << 7;
  const int tid = threadIdx.x;
  const int tx = tid & 15;
  const int ty = tid >> 4;
  float acc[8][8];
  #pragma unroll
  for (int i=0;i<8;i++)
    #pragma unroll
    for (int j=0;j<8;j++) acc[i][j]=0.f;

  for (int k0=0; k0<K; k0+=16){
    #pragma unroll
    for (int l=0;l<2;l++){
      int t = tid + (l<<8);
      int row = t >> 2;
      int kv = (t & 3) << 2;
      float4 v = *reinterpret_cast<const float4*>(A + (size_t)(m0+row)*K + k0 + kv);
      As[kv+0][row]=v.x; As[kv+1][row]=v.y; As[kv+2][row]=v.z; As[kv+3][row]=v.w;
    }
    #pragma unroll
    for (int l=0;l<2;l++){
      int t = tid + (l<<8);
      int row = t >> 2;
      int kv = (t & 3) << 2;
      float4 v = make_float4(0.f,0.f,0.f,0.f);
      if (n0+row < N)
        v = *reinterpret_cast<const float4*>(W + (size_t)(n0+row)*K + k0 + kv);
      Bs[kv+0][row]=v.x; Bs[kv+1][row]=v.y; Bs[kv+2][row]=v.z; Bs[kv+3][row]=v.w;
    }
    __syncthreads();
    #pragma unroll
    for (int kk=0; kk<16; kk++){
      float4 a0 = *reinterpret_cast<const float4*>(&As[kk][ty<<3]);
      float4 a1 = *reinterpret_cast<const float4*>(&As[kk][(ty<<3)+4]);
      float4 b0 = *reinterpret_cast<const float4*>(&Bs[kk][tx<<3]);
      float4 b1 = *reinterpret_cast<const float4*>(&Bs[kk][(tx<<3)+4]);
      float a[8]={a0.x,a0.y,a0.z,a0.w,a1.x,a1.y,a1.z,a1.w};
      float b[8]={b0.x,b0.y,b0.z,b0.w,b1.x,b1.y,b1.z,b1.w};
      #pragma unroll
      for (int i=0;i<8;i++)
        #pragma unroll
        for (int j=0;j<8;j++) acc[i][j] = fmaf(a[i], b[j], acc[i][j]);
    }
    __syncthreads();
  }
  #pragma unroll
  for (int i=0;i<8;i++){
    size_t m = (size_t)m0 + (ty<<3) + i;
    #pragma unroll
    for (int j=0;j<8;j++){
      int n = n0 + (tx<<3) + j;
      if (n < N){
        float v = acc[i][j] + bias[n];
        if (relu) v = fmaxf(v, 0.f);
        C[m*(size_t)ldc + n] = v;
      }
    }
  }
}

// -------- prev_active: last active row index per (step,track) --------------
__global__ void prev_kernel(const int* __restrict__ mask){
  __shared__ unsigned char sm[B_];
  int tr = blockIdx.x;
  for (int s = threadIdx.x; s < B_; s += blockDim.x)
    sm[s] = (unsigned char)(mask[(size_t)s*T_ + tr] != 0);
  __syncthreads();
  if (threadIdx.x == 0){
    int last = -1;
    for (int s = 0; s < B_; s++){
      g_PREV[s*T_ + tr] = last;
      if (sm[s]) last = s*T_ + tr;
    }
  }
}

// --------------------- gi for coord GRU (K=4) -------------------------------
__global__ void gic_kernel(const float* __restrict__ coord,
                           const float* __restrict__ Wic,
                           const float* __restrict__ bic){
  size_t idx = (size_t)blockIdx.x*blockDim.x + threadIdx.x;
  if (idx >= (size_t)R_*GC3_) return;
  int r = (int)(idx / GC3_), n = (int)(idx % GC3_);
  const float* c = coord + (size_t)r*4;
  const float* w = Wic + (size_t)n*4;
  g_GIC[idx] = c[0]*w[0]+c[1]*w[1]+c[2]*w[2]+c[3]*w[3] + bic[n];
}

// -------------- gather: hp[r] = attn[prev]*H[prev] (or 0) -------------------
__global__ void gather_kernel(const float4* __restrict__ src,
                              const float*  __restrict__ attn,
                              float4* __restrict__ dst, int w4, int first){
  size_t i = (size_t)blockIdx.x*blockDim.x + threadIdx.x;
  if (i >= (size_t)R_*w4) return;
  float4 o = make_float4(0.f,0.f,0.f,0.f);
  if (!first){
    int r = (int)(i / w4);
    int c = (int)(i - (size_t)r*w4);
    int p = g_PREV[r];
    if (p >= 0){
      float a = attn[p];
      float4 v = src[(size_t)p*w4 + c];
      o.x=a*v.x; o.y=a*v.y; o.z=a*v.z; o.w=a*v.w;
    }
  }
  dst[i] = o;
}

// ----------------------- GRU combine (r,z,n order) --------------------------
__global__ void combine_kernel(const float* __restrict__ GI,
                               const float* __restrict__ GH,
                               const float* __restrict__ HP,
                               float* __restrict__ Hout, int Hd){
  size_t i = (size_t)blockIdx.x*blockDim.x + threadIdx.x;
  if (i >= (size_t)R_*Hd) return;
  int r = (int)(i / Hd), c = (int)(i % Hd);
  const float* gi = GI + (size_t)r*3*Hd;
  const float* gh = GH + (size_t)r*3*Hd;
  float rg = sigm(gi[c]       + gh[c]);
  float z  = sigm(gi[Hd+c]    + gh[Hd+c]);
  float n  = tanhf(gi[2*Hd+c] + rg*gh[2*Hd+c]);
  float hp = HP[i];
  Hout[i] = (1.f - z)*n + z*hp;
}

// ------------------ attention scores: tanh(h)·w ------------------------------
__global__ void scores_kernel(const float* __restrict__ wev,
                              const float* __restrict__ wco){
  int r = blockIdx.x*8 + (threadIdx.x>>5);
  int lane = threadIdx.x & 31;
  const float* h0 = g_H0 + (size_t)r*H_;
  const float* h1 = g_H1 + (size_t)r*H_;
  float s0=0.f, s1=0.f;
  #pragma unroll
  for (int c=lane; c<H_; c+=32){
    float w = wev[c];
    s0 = fmaf(tanhf(h0[c]), w, s0);
    s1 = fmaf(tanhf(h1[c]), w, s1);
  }
  float sc = tanhf(g_HC[(size_t)r*HC_ + lane]) * wco[lane];
  s0 = wsum(s0); s1 = wsum(s1); sc = wsum(sc);
  if (lane == 0){ g_S0[r]=s0; g_S1[r]=s1; g_SC[r]=sc; }
}

// ---------------- masked softmax over tracks per step -----------------------
__global__ void softmax_kernel(const int* __restrict__ mask){
  int step = blockIdx.x*8 + (threadIdx.x>>5);
  int lane = threadIdx.x & 31;
  int row  = step*T_ + lane;
  bool valid = lane < T_;
  bool m = valid && (mask[(size_t)step*T_ + (valid?lane:0)] != 0);
  {
    float s = m ? g_S0[row] : -1e30f;
    float mx = wmax(s);
    float e = m ? expf(s - mx) : 0.f;
    float su = wsum(e);
    if (valid) g_A0[row] = e / fmaxf(su, 1e-9f);
  }
  {
    float s = m ? g_S1[row] : -1e30f;
    float mx = wmax(s);
    float e = m ? expf(s - mx) : 0.f;
    float su = wsum(e);
    if (valid) g_A1[row] = e / fmaxf(su, 1e-9f);
  }
  {
    float s = m ? g_SC[row] : -1e30f;
    float mx = wmax(s);
    float e = m ? expf(s - mx) : 0.f;
    float su = wsum(e);
    if (valid) g_AC[row] = e / fmaxf(su, 1e-9f);
  }
}

// ------------- logits (N=2), masked outs, CE partial sums -------------------
__global__ void logits_kernel(const float* __restrict__ F1,
                              const float* __restrict__ Wf2,
                              const float* __restrict__ bf2,
                              const int* __restrict__ labels,
                              const int* __restrict__ mask,
                              float* __restrict__ out){
  int r = blockIdx.x*8 + (threadIdx.x>>5);
  int lane = threadIdx.x & 31;
  __shared__ float sred[8];
  const float* f = F1 + (size_t)r*H_;
  float l0=0.f, l1=0.f;
  #pragma unroll
  for (int c=lane; c<H_; c+=32){
    float v = f[c];
    l0 = fmaf(v, Wf2[c],     l0);
    l1 = fmaf(v, Wf2[H_+c],  l1);
  }
  l0 = wsum(l0); l1 = wsum(l1);
  if (lane == 0){
    l0 += bf2[0]; l1 += bf2[1];
    bool m = mask[r] != 0;
    out[1 + 2*(size_t)r]     = m ? l0 : 0.f;
    out[1 + 2*(size_t)r + 1] = m ? l1 : 0.f;
    float ce = 0.f;
    if (m){
      float mx = fmaxf(l0, l1);
      float lse = mx + logf(expf(l0-mx) + expf(l1-mx));
      ce = lse - (labels[r] ? l1 : l0);
    }
    sred[threadIdx.x>>5] = ce;
  }
  __syncthreads();
  if (threadIdx.x == 0){
    float s = 0.f;
    #pragma unroll
    for (int i=0;i<8;i++) s += sred[i];
    g_partial[blockIdx.x] = s;
  }
}

__global__ void loss_final(float* __restrict__ out){
  __shared__ float sm[32];
  float s = 0.f;
  for (int i = threadIdx.x; i < NLOGB; i += blockDim.x) s += g_partial[i];
  s = wsum(s);
  if ((threadIdx.x & 31) == 0) sm[threadIdx.x >> 5] = s;
  __syncthreads();
  if (threadIdx.x < 32){
    float v = (threadIdx.x < (int)(blockDim.x>>5)) ? sm[threadIdx.x] : 0.f;
    v = wsum(v);
    if (threadIdx.x == 0) out[0] = v;
  }
}

// -------------------------------- launch ------------------------------------
static float* sym(const void* s){ void* p=nullptr; cudaGetSymbolAddress(&p, s); return (float*)p; }

extern "C" void kernel_launch(void* const* d_in, const int* in_sizes, int n_in,
                              void* d_out, int out_size)
{
  const float* feat   = (const float*)d_in[0];
  const float* coord  = (const float*)d_in[1];
  const int*   labels = (const int*)d_in[2];
  const int*   mask   = (const int*)d_in[3];      // bool widened to int32
  const float* Wi0=(const float*)d_in[4],  *Wh0=(const float*)d_in[5];
  const float* bi0=(const float*)d_in[6],  *bh0=(const float*)d_in[7];
  const float* Wi1=(const float*)d_in[8],  *Wh1=(const float*)d_in[9];
  const float* bi1=(const float*)d_in[10], *bh1=(const float*)d_in[11];
  const float* Wic=(const float*)d_in[12], *Whc=(const float*)d_in[13];
  const float* bic=(const float*)d_in[14], *bhc=(const float*)d_in[15];
  const float* We =(const float*)d_in[16], *be =(const float*)d_in[17];
  const float* Wc =(const float*)d_in[18], *bc =(const float*)d_in[19];
  const float* Wf1=(const float*)d_in[20], *bf1=(const float*)d_in[21];
  const float* Wf2=(const float*)d_in[22], *bf2=(const float*)d_in[23];
  const float* wev=(const float*)d_in[24], *wco=(const float*)d_in[25];
  float* out = (float*)d_out;

  float* GI0 = sym(g_GI0); float* GHA = sym(g_GHA); float* GI1 = sym(g_GI1);
  float* GIC = sym(g_GIC); float* GHC = sym(g_GHC);
  float* HP0 = sym(g_HP0); float* HP1 = sym(g_HP1); float* HPC = sym(g_HPC);
  float* H0  = sym(g_H0);  float* H1  = sym(g_H1);  float* HC  = sym(g_HC);
  float* A0  = sym(g_A0);  float* A1  = sym(g_A1);  float* AC  = sym(g_AC);

  const int MT = R_/128;            // 960 M-tiles
  dim3 g768(6, MT), g256(2, MT), g96(1, MT);
  dim3 gfuse(4, MT);                // fused: 4 unit-tiles of 64

  // one-time precompute (fp32: feeds the exact final pass & head)
  prev_kernel<<<T_, 256>>>(mask);
  sgemm_nt<<<g768, 256>>>(feat, Wi0, bi0, GI0, G3_, 64, G3_, 0);
  gic_kernel<<<((size_t)R_*GC3_ + 255)/256, 256>>>(coord, Wic, bic);

  const int gbH  = (R_*(H_/4)  + 255)/256;   // gather grid, w4=64
  const int gbHC = (R_*(HC_/4) + 255)/256;   // w4=8
  const int ebH  = (R_*H_  + 255)/256;
  const int ebHC = (R_*HC_ + 255)/256;

  for (int p = 0; p < PASSES; p++){
    int first = (p == 0);
    bool tc = (p < TC_PASSES);
    gather_kernel<<<gbH , 256>>>((const float4*)H0, A0, (float4*)HP0, H_/4,  first);
    gather_kernel<<<gbH , 256>>>((const float4*)H1, A1, (float4*)HP1, H_/4,  first);
    gather_kernel<<<gbHC, 256>>>((const float4*)HC, AC, (float4*)HPC, HC_/4, first);

    if (tc){
      // layer 0: fused gh0-GEMM + GRU combine -> H0
      tgemm_gru<<<gfuse, 256>>>(HP0, Wh0, bh0, GI0, H0);
      // gi1 = H0 @ Wi1^T + bi1 (gate-major)
      tgemm_nt<<<g768, 256>>>(H0, Wi1, bi1, GI1, G3_, H_, G3_);
      // layer 1: fused gh1-GEMM + GRU combine -> H1
      tgemm_gru<<<gfuse, 256>>>(HP1, Wh1, bh1, GI1, H1);
    } else {
      // exact fp32 pass (proven path)
      sgemm_nt<<<g768, 256>>>(HP0, Wh0, bh0, GHA, G3_, H_, G3_, 0);
      combine_kernel<<<ebH, 256>>>(GI0, GHA, HP0, H0, H_);
      sgemm_nt<<<g768, 256>>>(H0,  Wi1, bi1, GI1, G3_, H_, G3_, 0);
      sgemm_nt<<<g768, 256>>>(HP1, Wh1, bh1, GHA, G3_, H_, G3_, 0);
      combine_kernel<<<ebH, 256>>>(GI1, GHA, HP1, H1, H_);
    }

    // coord GRU (tiny, fp32 always)
    sgemm_nt<<<g96, 256>>>(HPC, Whc, bhc, GHC, GC3_, HC_, GC3_, 0);
    combine_kernel<<<ebHC, 256>>>(GIC, GHC, HPC, HC, HC_);

    if (p < PASSES-1){   // final pass attention outputs are unused
      scores_kernel<<<R_/8, 256>>>(wev, wco);
      softmax_kernel<<<B_/8, 256>>>(mask);
    }
  }

  // output head (once, fp32): comb = [H1@We^T+be | HC@Wc^T+bc] into GHA [R,512]
  sgemm_nt<<<g256, 256>>>(H1, We, be, GHA,       H_, H_,  512, 0);
  sgemm_nt<<<g256, 256>>>(HC, Wc, bc, GHA + 256, H_, HC_, 512, 0);
  // f1 = relu(comb@Wf1^T+bf1) into GI1 as [R,256]
  sgemm_nt<<<g256, 256>>>(GHA, Wf1, bf1, GI1, H_, 512, H_, 1);
  logits_kernel<<<R_/8, 256>>>(GI1, Wf2, bf2, labels, mask, out);
  loss_final<<<1, 1024>>>(out);
}